// round 15
// baseline (speedup 1.0000x reference)
#include <cuda_runtime.h>
#include <cuda_fp16.h>
#include <math.h>
#include <stdint.h>

#define BATCH 4
#define S_LEN 2048
#define D_DIM 1024
#define NH    16
#define DH    64
#define M_TOT (BATCH*S_LEN)

__device__ __half g_Qh[BATCH*NH*S_LEN*DH];   // holds Q * 0.125*log2(e)
__device__ __half g_Kh[BATCH*NH*S_LEN*DH];
__device__ __half g_VTh[BATCH*NH*DH*S_LEN];  // [b,h][dh][S]
__device__ __half g_Hh[M_TOT*D_DIM];
__device__ __half g_Xh[M_TOT*D_DIM];
__device__ __half g_Wh[4*D_DIM*D_DIM];
__device__ float2 g_tab[S_LEN*(D_DIM/2)];

__device__ __forceinline__ unsigned pk(float a, float b){
    __half2 h = __floats2half2_rn(a, b); return *(unsigned*)&h;
}
__device__ __forceinline__ float ex2(float x){
    float y; asm("ex2.approx.f32 %0, %1;" : "=f"(y) : "f"(x)); return y;
}
__device__ __forceinline__ unsigned ex2h2(unsigned x){
    unsigned y; asm("ex2.approx.f16x2 %0, %1;" : "=r"(y) : "r"(x)); return y;
}
__device__ __forceinline__ uint32_t smem_u32(const void* p){
    uint32_t a;
    asm("{ .reg .u64 t; cvta.to.shared.u64 t, %1; cvt.u32.u64 %0, t; }" : "=r"(a) : "l"(p));
    return a;
}
__device__ __forceinline__ void cp16(uint32_t dst, const void* src){
    asm volatile("cp.async.cg.shared.global [%0], [%1], 16;" :: "r"(dst), "l"(src) : "memory");
}
#define CP_COMMIT() asm volatile("cp.async.commit_group;" ::: "memory")
#define CP_WAIT0()  asm volatile("cp.async.wait_group 0;" ::: "memory")

__device__ __forceinline__ void mma16(float* c, const unsigned* a, const unsigned* b){
    asm volatile("mma.sync.aligned.m16n8k16.row.col.f32.f16.f16.f32 "
        "{%0,%1,%2,%3}, {%4,%5,%6,%7}, {%8,%9}, {%0,%1,%2,%3};"
        : "+f"(c[0]), "+f"(c[1]), "+f"(c[2]), "+f"(c[3])
        : "r"(a[0]), "r"(a[1]), "r"(a[2]), "r"(a[3]), "r"(b[0]), "r"(b[1]));
}

__global__ void rope_table_kernel(){
    int idx = blockIdx.x*blockDim.x + threadIdx.x;
    if (idx >= S_LEN*512) return;
    int s = idx >> 9, p = idx & 511;
    double inv = exp(-((double)(2*p)/(double)D_DIM)*log(10000.0));
    float sn, cs; sincosf((float)s*(float)inv, &sn, &cs);
    g_tab[idx] = make_float2(cs, sn);
}

__global__ void conv_f16(const float* __restrict__ src, __half* __restrict__ dst, int n8){
    int i = blockIdx.x*blockDim.x + threadIdx.x;
    if (i >= n8) return;
    const float4* s = (const float4*)src + (size_t)i*2;
    float4 v0 = s[0], v1 = s[1];
    uint4 o;
    o.x = pk(v0.x, v0.y); o.y = pk(v0.z, v0.w);
    o.z = pk(v1.x, v1.y); o.w = pk(v1.z, v1.w);
    ((uint4*)dst)[i] = o;
}

// ============ fp16 GEMM: out = A[M,1024] @ W[N,1024]^T + bias ============
// MODE 0: fp32 [M,N]+bias; MODE 2: RoPE+qscale+half scatter [B,H,S,dh]; MODE 3: half transposed [B,H,dh,S]
template<int MODE>
__global__ __launch_bounds__(128,2) void gemm_h(
    const __half* __restrict__ A, const __half* __restrict__ W,
    const float* __restrict__ bias, void* __restrict__ outv, float qs)
{
    __shared__ unsigned As[2][8*136], Bs[2][8*136];
    int tid = threadIdx.x, lane = tid & 31, w = tid >> 5;
    int rr = lane >> 2, cb = lane & 3;
    int wm = (w >> 1)*64, wn = (w & 1)*64;
    int m0 = blockIdx.y*128, n0 = blockIdx.x*128;

    float acc[4][8][4];
    #pragma unroll
    for (int i=0;i<4;i++)
        #pragma unroll
        for (int j=0;j<8;j++)
            #pragma unroll
            for (int e=0;e<4;e++) acc[i][j][e] = 0.f;

    const uint4* Ar[2]; const uint4* Wr[2];
    int mm[2], kk[2];
    #pragma unroll
    for (int l=0;l<2;l++){
        int slot = tid + l*128;
        mm[l] = slot >> 1; kk[l] = slot & 1;
        Ar[l] = (const uint4*)A + (size_t)(m0+mm[l])*128;
        Wr[l] = (const uint4*)W + (size_t)(n0+mm[l])*128;
    }

    uint4 av[2], bv[2];
    #pragma unroll
    for (int l=0;l<2;l++){ av[l] = Ar[l][kk[l]]; bv[l] = Wr[l][kk[l]]; }
    #pragma unroll
    for (int l=0;l<2;l++){
        const unsigned* a4 = (const unsigned*)&av[l];
        const unsigned* b4 = (const unsigned*)&bv[l];
        #pragma unroll
        for (int j=0;j<4;j++){
            As[0][(kk[l]*4+j)*136 + ((mm[l] + 8*kk[l]) & 127)] = a4[j];
            Bs[0][(kk[l]*4+j)*136 + ((mm[l] + 8*kk[l]) & 127)] = b4[j];
        }
    }
    __syncthreads();

    for (int it = 0; it < 64; it++){
        int cur = it & 1;
        if (it + 1 < 64){
            #pragma unroll
            for (int l=0;l<2;l++){
                av[l] = Ar[l][(it+1)*2 + kk[l]];
                bv[l] = Wr[l][(it+1)*2 + kk[l]];
            }
        }
        unsigned a[4][4], b[8][2];
        #pragma unroll
        for (int fm = 0; fm < 4; fm++){
            int r = wm + rr + fm*16;
            a[fm][0] = As[cur][cb*136 + (r & 127)];
            a[fm][1] = As[cur][cb*136 + ((r+8) & 127)];
            a[fm][2] = As[cur][(cb+4)*136 + ((r+8) & 127)];
            a[fm][3] = As[cur][(cb+4)*136 + ((r+16) & 127)];
        }
        #pragma unroll
        for (int fn = 0; fn < 8; fn++){
            int n = wn + rr + fn*8;
            b[fn][0] = Bs[cur][cb*136 + (n & 127)];
            b[fn][1] = Bs[cur][(cb+4)*136 + ((n+8) & 127)];
        }
        #pragma unroll
        for (int fm = 0; fm < 4; fm++)
            #pragma unroll
            for (int fn = 0; fn < 8; fn++)
                mma16(acc[fm][fn], a[fm], b[fn]);
        if (it + 1 < 64){
            int nxt = cur ^ 1;
            #pragma unroll
            for (int l=0;l<2;l++){
                const unsigned* a4 = (const unsigned*)&av[l];
                const unsigned* b4 = (const unsigned*)&bv[l];
                #pragma unroll
                for (int j=0;j<4;j++){
                    As[nxt][(kk[l]*4+j)*136 + ((mm[l] + 8*kk[l]) & 127)] = a4[j];
                    Bs[nxt][(kk[l]*4+j)*136 + ((mm[l] + 8*kk[l]) & 127)] = b4[j];
                }
            }
            __syncthreads();
        }
    }

    #pragma unroll
    for (int fn = 0; fn < 8; fn++){
        int colg = n0 + wn + fn*8 + cb*2;
        float b0v = bias[colg], b1v = bias[colg+1];
        #pragma unroll
        for (int fm = 0; fm < 4; fm++){
            #pragma unroll
            for (int half = 0; half < 2; half++){
                int mr = m0 + wm + fm*16 + rr + half*8;
                float v0 = acc[fm][fn][half*2+0] + b0v;
                float v1 = acc[fm][fn][half*2+1] + b1v;
                int srow = mr & (S_LEN-1);
                int bb = mr >> 11, hh = colg >> 6, dd = colg & 63;
                if (MODE == 2){
                    float2 cs = g_tab[srow*512 + (colg >> 1)];
                    float e = v0*cs.x - v1*cs.y;
                    float d = v0*cs.y + v1*cs.x;
                    v0 = e*qs; v1 = d*qs;
                }
                if (MODE == 0){
                    *(float2*)((float*)outv + (size_t)mr*D_DIM + colg) = make_float2(v0, v1);
                } else if (MODE == 2){
                    ((unsigned*)outv)[((size_t)(bb*NH+hh)*S_LEN + srow)*32 + (dd>>1)] = pk(v0, v1);
                } else {  // MODE 3: V transposed [b,h][dh][S]
                    __half* ov = (__half*)outv + ((size_t)(bb*NH+hh)*DH + dd)*S_LEN + srow;
                    ov[0] = __float2half(v0);
                    ov[S_LEN] = __float2half(v1);
                }
            }
        }
    }
}

// ============ fp16 flash attention: 8 warps x 32q x 64k, cp.async K/V, 2 CTAs/SM ============
__global__ __launch_bounds__(256,2) void attn_h(
    const __half* __restrict__ Q, const __half* __restrict__ K,
    const __half* __restrict__ VT, __half* __restrict__ H)
{
    extern __shared__ unsigned sm[];
    // layout (words): K: [0, 2*2304), V: [4608, +2*2304)
    int tid = threadIdx.x, lane = tid & 31, w = tid >> 5;
    int rr = lane >> 2, cb = lane & 3;
    int qb = blockIdx.x, hd = blockIdx.y, b = blockIdx.z;
    int bh = b*NH + hd;

    const unsigned* Qw = (const unsigned*)(Q + ((size_t)bh*S_LEN + qb*256 + w*32)*DH);
    const uint4* Kg = (const uint4*)(K + (size_t)bh*S_LEN*DH);
    const uint4* Vg = (const uint4*)(VT + (size_t)bh*DH*S_LEN);

    int kp0 = tid >> 3, cq0 = tid & 7;           // slot 0: rows 0..31
    int kp1 = kp0 + 32;                          // slot 1: rows 32..63
    uint32_t sb = smem_u32(sm);
    uint32_t kd0 = sb + (kp0*36 + cq0*4)*4, kd1 = sb + (kp1*36 + cq0*4)*4;
    uint32_t vd0 = kd0 + 4608*4, vd1 = kd1 + 4608*4;

    // Q pre-scaled by 0.125*log2e in the projection epilogue
    unsigned q[2][4][4];
    #pragma unroll
    for (int fm = 0; fm < 2; fm++){
        int r0 = fm*16 + rr;
        #pragma unroll
        for (int ks = 0; ks < 4; ks++){
            int kw = ks*8 + cb;
            q[fm][ks][0] = Qw[r0*32 + kw];
            q[fm][ks][1] = Qw[(r0+8)*32 + kw];
            q[fm][ks][2] = Qw[r0*32 + kw + 4];
            q[fm][ks][3] = Qw[(r0+8)*32 + kw + 4];
        }
    }

    float m_[2][2], l_[2][2], o[2][8][4];
    #pragma unroll
    for (int fm=0;fm<2;fm++)
        #pragma unroll
        for (int hh=0;hh<2;hh++){ m_[fm][hh] = -1e30f; l_[fm][hh] = 0.f; }
    #pragma unroll
    for (int fm=0;fm<2;fm++)
        #pragma unroll
        for (int fn=0;fn<8;fn++)
            #pragma unroll
            for (int e=0;e<4;e++) o[fm][fn][e] = 0.f;

    // prologue: cp.async tile 0 into buffer 0
    cp16(kd0, Kg + (size_t)kp0*8 + cq0);
    cp16(kd1, Kg + (size_t)kp1*8 + cq0);
    cp16(vd0, Vg + (size_t)kp0*256 + cq0);
    cp16(vd1, Vg + (size_t)kp1*256 + cq0);
    CP_COMMIT();
    CP_WAIT0();
    __syncthreads();

    for (int t = 0; t < 32; t++){
        int cur = t & 1;
        const unsigned* Kc = sm + cur*2304;
        const unsigned* Vc = sm + 4608 + cur*2304;
        if (t + 1 < 32){
            uint32_t off = (uint32_t)((cur^1)*2304*4);
            cp16(kd0 + off, Kg + (size_t)((t+1)*64 + kp0)*8 + cq0);
            cp16(kd1 + off, Kg + (size_t)((t+1)*64 + kp1)*8 + cq0);
            cp16(vd0 + off, Vg + (size_t)kp0*256 + (t+1)*8 + cq0);
            cp16(vd1 + off, Vg + (size_t)kp1*256 + (t+1)*8 + cq0);
            CP_COMMIT();
        }

        float s[2][8][4];
        #pragma unroll
        for (int fm=0;fm<2;fm++)
            #pragma unroll
            for (int fn=0;fn<8;fn++)
                #pragma unroll
                for (int e=0;e<4;e++) s[fm][fn][e] = 0.f;

        #pragma unroll
        for (int ks = 0; ks < 4; ks++){
            int kw = ks*8 + cb;
            #pragma unroll
            for (int fn = 0; fn < 8; fn++){
                int n = fn*8 + rr;
                unsigned bb[2];
                bb[0] = Kc[n*36 + kw];
                bb[1] = Kc[n*36 + kw + 4];
                mma16(s[0][fn], q[0][ks], bb);
                mma16(s[1][fn], q[1][ks], bb);
            }
        }

        // base-2 online softmax; exponentials in f16x2 (packed P fragments fall out)
        unsigned p2[2][8][2];
        #pragma unroll
        for (int fm = 0; fm < 2; fm++)
            #pragma unroll
            for (int hh = 0; hh < 2; hh++){
                float rm = -1e30f;
                #pragma unroll
                for (int fn = 0; fn < 8; fn++)
                    rm = fmaxf(rm, fmaxf(s[fm][fn][hh*2], s[fm][fn][hh*2+1]));
                rm = fmaxf(rm, __shfl_xor_sync(0xffffffffu, rm, 1));
                rm = fmaxf(rm, __shfl_xor_sync(0xffffffffu, rm, 2));
                float mn = fmaxf(m_[fm][hh], rm);
                float sum = 0.f;
                #pragma unroll
                for (int fn = 0; fn < 8; fn++){
                    float d0 = s[fm][fn][hh*2]   - mn;
                    float d1 = s[fm][fn][hh*2+1] - mn;
                    unsigned pe = ex2h2(pk(d0, d1));
                    p2[fm][fn][hh] = pe;
                    float2 f = __half22float2(*(__half2*)&pe);
                    sum += f.x + f.y;
                }
                sum += __shfl_xor_sync(0xffffffffu, sum, 1);
                sum += __shfl_xor_sync(0xffffffffu, sum, 2);
                float alpha = ex2(m_[fm][hh] - mn);
                l_[fm][hh] = l_[fm][hh]*alpha + sum;
                m_[fm][hh] = mn;
                #pragma unroll
                for (int fn = 0; fn < 8; fn++){
                    o[fm][fn][hh*2]   *= alpha;
                    o[fm][fn][hh*2+1] *= alpha;
                }
            }

        // PV: A-fragments are the packed exp results directly
        #pragma unroll
        for (int ks = 0; ks < 4; ks++){
            int kw = ks*8 + cb;
            unsigned a[2][4];
            #pragma unroll
            for (int fm = 0; fm < 2; fm++){
                a[fm][0] = p2[fm][2*ks][0];
                a[fm][1] = p2[fm][2*ks][1];
                a[fm][2] = p2[fm][2*ks+1][0];
                a[fm][3] = p2[fm][2*ks+1][1];
            }
            #pragma unroll
            for (int fn = 0; fn < 8; fn++){
                int n = fn*8 + rr;
                unsigned bb[2];
                bb[0] = Vc[n*36 + kw];
                bb[1] = Vc[n*36 + kw + 4];
                mma16(o[0][fn], a[0], bb);
                mma16(o[1][fn], a[1], bb);
            }
        }

        if (t + 1 < 32){
            CP_WAIT0();
            __syncthreads();
        }
    }

    unsigned* Hw = (unsigned*)H;
    #pragma unroll
    for (int fm = 0; fm < 2; fm++)
        #pragma unroll
        for (int hh = 0; hh < 2; hh++){
            float inv = 1.f / l_[fm][hh];
            int sg = qb*256 + w*32 + fm*16 + rr + 8*hh;
            size_t base = ((size_t)b*S_LEN + sg)*512 + hd*32;
            #pragma unroll
            for (int fn = 0; fn < 8; fn++)
                Hw[base + fn*4 + cb] = pk(o[fm][fn][hh*2]*inv, o[fm][fn][hh*2+1]*inv);
        }
}

extern "C" void kernel_launch(void* const* d_in, const int* in_sizes, int n_in,
                              void* d_out, int out_size)
{
    const float* X  = (const float*)d_in[0];
    const float* Wq = (const float*)d_in[1];
    const float* bq = (const float*)d_in[2];
    const float* Wk = (const float*)d_in[3];
    const float* bk = (const float*)d_in[4];
    const float* Wv = (const float*)d_in[5];
    const float* bv = (const float*)d_in[6];
    const float* Wo = (const float*)d_in[7];
    const float* bo = (const float*)d_in[8];
    float* out = (float*)d_out;

    __half *gq, *gk, *gvt, *gh, *gx, *gw;
    cudaGetSymbolAddress((void**)&gq, g_Qh);
    cudaGetSymbolAddress((void**)&gk, g_Kh);
    cudaGetSymbolAddress((void**)&gvt, g_VTh);
    cudaGetSymbolAddress((void**)&gh, g_Hh);
    cudaGetSymbolAddress((void**)&gx, g_Xh);
    cudaGetSymbolAddress((void**)&gw, g_Wh);

    const int attn_smem = 4*2304*4;   // 36864 B per CTA
    cudaFuncSetAttribute(attn_h, cudaFuncAttributeMaxDynamicSharedMemorySize, attn_smem);

    rope_table_kernel<<<(S_LEN*512 + 255)/256, 256>>>();

    const int X8 = M_TOT*D_DIM/8, W8 = D_DIM*D_DIM/8;
    conv_f16<<<(X8 + 255)/256, 256>>>(X, gx, X8);
    conv_f16<<<(W8 + 255)/256, 256>>>(Wq, gw + 0*D_DIM*D_DIM, W8);
    conv_f16<<<(W8 + 255)/256, 256>>>(Wk, gw + 1*D_DIM*D_DIM, W8);
    conv_f16<<<(W8 + 255)/256, 256>>>(Wv, gw + 2*D_DIM*D_DIM, W8);
    conv_f16<<<(W8 + 255)/256, 256>>>(Wo, gw + 3*D_DIM*D_DIM, W8);

    const float QS = 0.18033688011112042f;   // 0.125 * log2(e)
    dim3 ggrid(D_DIM/128, M_TOT/128);   // (8, 64)
    gemm_h<2><<<ggrid, 128>>>(gx, gw + 0*D_DIM*D_DIM, bq, gq, QS);
    gemm_h<2><<<ggrid, 128>>>(gx, gw + 1*D_DIM*D_DIM, bk, gk, 1.0f);
    gemm_h<3><<<ggrid, 128>>>(gx, gw + 2*D_DIM*D_DIM, bv, gvt, 1.0f);

    attn_h<<<dim3(S_LEN/256, NH, BATCH), 256, attn_smem>>>(gq, gk, gvt, gh);

    gemm_h<0><<<ggrid, 128>>>(gh, gw + 3*D_DIM*D_DIM, bo, out, 1.0f);
}

// round 16
// speedup vs baseline: 1.3097x; 1.3097x over previous
#include <cuda_runtime.h>
#include <cuda_fp16.h>
#include <math.h>
#include <stdint.h>

#define BATCH 4
#define S_LEN 2048
#define D_DIM 1024
#define NH    16
#define DH    64
#define M_TOT (BATCH*S_LEN)

__device__ __half g_Qh[BATCH*NH*S_LEN*DH];   // holds Q * 0.125*log2(e)
__device__ __half g_Kh[BATCH*NH*S_LEN*DH];
__device__ __half g_VTh[BATCH*NH*DH*S_LEN];  // [b,h][dh][S]
__device__ __half g_Hh[M_TOT*D_DIM];
__device__ __half g_Xh[M_TOT*D_DIM];
__device__ __half g_Wh[4*D_DIM*D_DIM];
__device__ float2 g_tab[S_LEN*(D_DIM/2)];

__device__ __forceinline__ unsigned pk(float a, float b){
    __half2 h = __floats2half2_rn(a, b); return *(unsigned*)&h;
}
__device__ __forceinline__ float ex2(float x){
    float y; asm("ex2.approx.f32 %0, %1;" : "=f"(y) : "f"(x)); return y;
}
__device__ __forceinline__ unsigned ex2h2(unsigned x){
    unsigned y; asm("ex2.approx.f16x2 %0, %1;" : "=r"(y) : "r"(x)); return y;
}
__device__ __forceinline__ uint32_t smem_u32(const void* p){
    uint32_t a;
    asm("{ .reg .u64 t; cvta.to.shared.u64 t, %1; cvt.u32.u64 %0, t; }" : "=r"(a) : "l"(p));
    return a;
}
__device__ __forceinline__ void cp16(uint32_t dst, const void* src){
    asm volatile("cp.async.cg.shared.global [%0], [%1], 16;" :: "r"(dst), "l"(src) : "memory");
}
#define CP_COMMIT() asm volatile("cp.async.commit_group;" ::: "memory")
#define CP_WAIT0()  asm volatile("cp.async.wait_group 0;" ::: "memory")

__device__ __forceinline__ void mma16(float* c, const unsigned* a, const unsigned* b){
    asm volatile("mma.sync.aligned.m16n8k16.row.col.f32.f16.f16.f32 "
        "{%0,%1,%2,%3}, {%4,%5,%6,%7}, {%8,%9}, {%0,%1,%2,%3};"
        : "+f"(c[0]), "+f"(c[1]), "+f"(c[2]), "+f"(c[3])
        : "r"(a[0]), "r"(a[1]), "r"(a[2]), "r"(a[3]), "r"(b[0]), "r"(b[1]));
}

__global__ void rope_table_kernel(){
    int idx = blockIdx.x*blockDim.x + threadIdx.x;
    if (idx >= S_LEN*512) return;
    int s = idx >> 9, p = idx & 511;
    double inv = exp(-((double)(2*p)/(double)D_DIM)*log(10000.0));
    float sn, cs; sincosf((float)s*(float)inv, &sn, &cs);
    g_tab[idx] = make_float2(cs, sn);
}

__global__ void conv_f16(const float* __restrict__ src, __half* __restrict__ dst, int n8){
    int i = blockIdx.x*blockDim.x + threadIdx.x;
    if (i >= n8) return;
    const float4* s = (const float4*)src + (size_t)i*2;
    float4 v0 = s[0], v1 = s[1];
    uint4 o;
    o.x = pk(v0.x, v0.y); o.y = pk(v0.z, v0.w);
    o.z = pk(v1.x, v1.y); o.w = pk(v1.z, v1.w);
    ((uint4*)dst)[i] = o;
}

// ============ fp16 GEMM: out = A[M,1024] @ W[N,1024]^T + bias ============
// MODE 0: fp32 [M,N]+bias; MODE 2: RoPE+qscale+half scatter [B,H,S,dh]; MODE 3: half transposed [B,H,dh,S]
template<int MODE>
__global__ __launch_bounds__(128,2) void gemm_h(
    const __half* __restrict__ A, const __half* __restrict__ W,
    const float* __restrict__ bias, void* __restrict__ outv, float qs)
{
    __shared__ unsigned As[2][8*136], Bs[2][8*136];
    int tid = threadIdx.x, lane = tid & 31, w = tid >> 5;
    int rr = lane >> 2, cb = lane & 3;
    int wm = (w >> 1)*64, wn = (w & 1)*64;
    int m0 = blockIdx.y*128, n0 = blockIdx.x*128;

    float acc[4][8][4];
    #pragma unroll
    for (int i=0;i<4;i++)
        #pragma unroll
        for (int j=0;j<8;j++)
            #pragma unroll
            for (int e=0;e<4;e++) acc[i][j][e] = 0.f;

    const uint4* Ar[2]; const uint4* Wr[2];
    int mm[2], kk[2];
    #pragma unroll
    for (int l=0;l<2;l++){
        int slot = tid + l*128;
        mm[l] = slot >> 1; kk[l] = slot & 1;
        Ar[l] = (const uint4*)A + (size_t)(m0+mm[l])*128;
        Wr[l] = (const uint4*)W + (size_t)(n0+mm[l])*128;
    }

    uint4 av[2], bv[2];
    #pragma unroll
    for (int l=0;l<2;l++){ av[l] = Ar[l][kk[l]]; bv[l] = Wr[l][kk[l]]; }
    #pragma unroll
    for (int l=0;l<2;l++){
        const unsigned* a4 = (const unsigned*)&av[l];
        const unsigned* b4 = (const unsigned*)&bv[l];
        #pragma unroll
        for (int j=0;j<4;j++){
            As[0][(kk[l]*4+j)*136 + ((mm[l] + 8*kk[l]) & 127)] = a4[j];
            Bs[0][(kk[l]*4+j)*136 + ((mm[l] + 8*kk[l]) & 127)] = b4[j];
        }
    }
    __syncthreads();

    for (int it = 0; it < 64; it++){
        int cur = it & 1;
        if (it + 1 < 64){
            #pragma unroll
            for (int l=0;l<2;l++){
                av[l] = Ar[l][(it+1)*2 + kk[l]];
                bv[l] = Wr[l][(it+1)*2 + kk[l]];
            }
        }
        unsigned a[4][4], b[8][2];
        #pragma unroll
        for (int fm = 0; fm < 4; fm++){
            int r = wm + rr + fm*16;
            a[fm][0] = As[cur][cb*136 + (r & 127)];
            a[fm][1] = As[cur][cb*136 + ((r+8) & 127)];
            a[fm][2] = As[cur][(cb+4)*136 + ((r+8) & 127)];
            a[fm][3] = As[cur][(cb+4)*136 + ((r+16) & 127)];
        }
        #pragma unroll
        for (int fn = 0; fn < 8; fn++){
            int n = wn + rr + fn*8;
            b[fn][0] = Bs[cur][cb*136 + (n & 127)];
            b[fn][1] = Bs[cur][(cb+4)*136 + ((n+8) & 127)];
        }
        #pragma unroll
        for (int fm = 0; fm < 4; fm++)
            #pragma unroll
            for (int fn = 0; fn < 8; fn++)
                mma16(acc[fm][fn], a[fm], b[fn]);
        if (it + 1 < 64){
            int nxt = cur ^ 1;
            #pragma unroll
            for (int l=0;l<2;l++){
                const unsigned* a4 = (const unsigned*)&av[l];
                const unsigned* b4 = (const unsigned*)&bv[l];
                #pragma unroll
                for (int j=0;j<4;j++){
                    As[nxt][(kk[l]*4+j)*136 + ((mm[l] + 8*kk[l]) & 127)] = a4[j];
                    Bs[nxt][(kk[l]*4+j)*136 + ((mm[l] + 8*kk[l]) & 127)] = b4[j];
                }
            }
            __syncthreads();
        }
    }

    #pragma unroll
    for (int fn = 0; fn < 8; fn++){
        int colg = n0 + wn + fn*8 + cb*2;
        float b0v = bias[colg], b1v = bias[colg+1];
        #pragma unroll
        for (int fm = 0; fm < 4; fm++){
            #pragma unroll
            for (int half = 0; half < 2; half++){
                int mr = m0 + wm + fm*16 + rr + half*8;
                float v0 = acc[fm][fn][half*2+0] + b0v;
                float v1 = acc[fm][fn][half*2+1] + b1v;
                int srow = mr & (S_LEN-1);
                int bb = mr >> 11, hh = colg >> 6, dd = colg & 63;
                if (MODE == 2){
                    float2 cs = g_tab[srow*512 + (colg >> 1)];
                    float e = v0*cs.x - v1*cs.y;
                    float d = v0*cs.y + v1*cs.x;
                    v0 = e*qs; v1 = d*qs;
                }
                if (MODE == 0){
                    *(float2*)((float*)outv + (size_t)mr*D_DIM + colg) = make_float2(v0, v1);
                } else if (MODE == 2){
                    ((unsigned*)outv)[((size_t)(bb*NH+hh)*S_LEN + srow)*32 + (dd>>1)] = pk(v0, v1);
                } else {  // MODE 3: V transposed [b,h][dh][S]
                    __half* ov = (__half*)outv + ((size_t)(bb*NH+hh)*DH + dd)*S_LEN + srow;
                    ov[0] = __float2half(v0);
                    ov[S_LEN] = __float2half(v1);
                }
            }
        }
    }
}

// ============ fp16 flash attention: 8 warps x 32q x 64k, cp.async K/V, 1 CTA/SM ============
__global__ __launch_bounds__(256,1) void attn_h(
    const __half* __restrict__ Q, const __half* __restrict__ K,
    const __half* __restrict__ VT, __half* __restrict__ H)
{
    extern __shared__ unsigned sm[];
    // layout (words): K: [0, 2*2304), V: [4608, +2*2304)
    int tid = threadIdx.x, lane = tid & 31, w = tid >> 5;
    int rr = lane >> 2, cb = lane & 3;
    int qb = blockIdx.x, hd = blockIdx.y, b = blockIdx.z;
    int bh = b*NH + hd;

    const unsigned* Qw = (const unsigned*)(Q + ((size_t)bh*S_LEN + qb*256 + w*32)*DH);
    const uint4* Kg = (const uint4*)(K + (size_t)bh*S_LEN*DH);
    const uint4* Vg = (const uint4*)(VT + (size_t)bh*DH*S_LEN);

    int kp0 = tid >> 3, cq0 = tid & 7;           // slot 0: rows 0..31
    int kp1 = kp0 + 32;                          // slot 1: rows 32..63
    uint32_t sb = smem_u32(sm);
    uint32_t kd0 = sb + (kp0*36 + cq0*4)*4, kd1 = sb + (kp1*36 + cq0*4)*4;
    uint32_t vd0 = kd0 + 4608*4, vd1 = kd1 + 4608*4;

    // Q pre-scaled by 0.125*log2e in the projection epilogue
    unsigned q[2][4][4];
    #pragma unroll
    for (int fm = 0; fm < 2; fm++){
        int r0 = fm*16 + rr;
        #pragma unroll
        for (int ks = 0; ks < 4; ks++){
            int kw = ks*8 + cb;
            q[fm][ks][0] = Qw[r0*32 + kw];
            q[fm][ks][1] = Qw[(r0+8)*32 + kw];
            q[fm][ks][2] = Qw[r0*32 + kw + 4];
            q[fm][ks][3] = Qw[(r0+8)*32 + kw + 4];
        }
    }

    float m_[2][2], l_[2][2], o[2][8][4];
    #pragma unroll
    for (int fm=0;fm<2;fm++)
        #pragma unroll
        for (int hh=0;hh<2;hh++){ m_[fm][hh] = -1e30f; l_[fm][hh] = 0.f; }
    #pragma unroll
    for (int fm=0;fm<2;fm++)
        #pragma unroll
        for (int fn=0;fn<8;fn++)
            #pragma unroll
            for (int e=0;e<4;e++) o[fm][fn][e] = 0.f;

    // prologue: cp.async tile 0 into buffer 0
    cp16(kd0, Kg + (size_t)kp0*8 + cq0);
    cp16(kd1, Kg + (size_t)kp1*8 + cq0);
    cp16(vd0, Vg + (size_t)kp0*256 + cq0);
    cp16(vd1, Vg + (size_t)kp1*256 + cq0);
    CP_COMMIT();
    CP_WAIT0();
    __syncthreads();

    for (int t = 0; t < 32; t++){
        int cur = t & 1;
        const unsigned* Kc = sm + cur*2304;
        const unsigned* Vc = sm + 4608 + cur*2304;
        if (t + 1 < 32){
            uint32_t off = (uint32_t)((cur^1)*2304*4);
            cp16(kd0 + off, Kg + (size_t)((t+1)*64 + kp0)*8 + cq0);
            cp16(kd1 + off, Kg + (size_t)((t+1)*64 + kp1)*8 + cq0);
            cp16(vd0 + off, Vg + (size_t)kp0*256 + (t+1)*8 + cq0);
            cp16(vd1 + off, Vg + (size_t)kp1*256 + (t+1)*8 + cq0);
            CP_COMMIT();
        }

        float s[2][8][4];
        #pragma unroll
        for (int fm=0;fm<2;fm++)
            #pragma unroll
            for (int fn=0;fn<8;fn++)
                #pragma unroll
                for (int e=0;e<4;e++) s[fm][fn][e] = 0.f;

        #pragma unroll
        for (int ks = 0; ks < 4; ks++){
            int kw = ks*8 + cb;
            #pragma unroll
            for (int fn = 0; fn < 8; fn++){
                int n = fn*8 + rr;
                unsigned bb[2];
                bb[0] = Kc[n*36 + kw];
                bb[1] = Kc[n*36 + kw + 4];
                mma16(s[0][fn], q[0][ks], bb);
                mma16(s[1][fn], q[1][ks], bb);
            }
        }

        // base-2 online softmax; exponentials in f16x2 (packed P fragments fall out)
        unsigned p2[2][8][2];
        #pragma unroll
        for (int fm = 0; fm < 2; fm++)
            #pragma unroll
            for (int hh = 0; hh < 2; hh++){
                float rm = -1e30f;
                #pragma unroll
                for (int fn = 0; fn < 8; fn++)
                    rm = fmaxf(rm, fmaxf(s[fm][fn][hh*2], s[fm][fn][hh*2+1]));
                rm = fmaxf(rm, __shfl_xor_sync(0xffffffffu, rm, 1));
                rm = fmaxf(rm, __shfl_xor_sync(0xffffffffu, rm, 2));
                float mn = fmaxf(m_[fm][hh], rm);
                float sum = 0.f;
                #pragma unroll
                for (int fn = 0; fn < 8; fn++){
                    float d0 = s[fm][fn][hh*2]   - mn;
                    float d1 = s[fm][fn][hh*2+1] - mn;
                    unsigned pe = ex2h2(pk(d0, d1));
                    p2[fm][fn][hh] = pe;
                    float2 f = __half22float2(*(__half2*)&pe);
                    sum += f.x + f.y;
                }
                sum += __shfl_xor_sync(0xffffffffu, sum, 1);
                sum += __shfl_xor_sync(0xffffffffu, sum, 2);
                float alpha = ex2(m_[fm][hh] - mn);
                l_[fm][hh] = l_[fm][hh]*alpha + sum;
                m_[fm][hh] = mn;
                #pragma unroll
                for (int fn = 0; fn < 8; fn++){
                    o[fm][fn][hh*2]   *= alpha;
                    o[fm][fn][hh*2+1] *= alpha;
                }
            }

        // PV: A-fragments are the packed exp results directly
        #pragma unroll
        for (int ks = 0; ks < 4; ks++){
            int kw = ks*8 + cb;
            unsigned a[2][4];
            #pragma unroll
            for (int fm = 0; fm < 2; fm++){
                a[fm][0] = p2[fm][2*ks][0];
                a[fm][1] = p2[fm][2*ks][1];
                a[fm][2] = p2[fm][2*ks+1][0];
                a[fm][3] = p2[fm][2*ks+1][1];
            }
            #pragma unroll
            for (int fn = 0; fn < 8; fn++){
                int n = fn*8 + rr;
                unsigned bb[2];
                bb[0] = Vc[n*36 + kw];
                bb[1] = Vc[n*36 + kw + 4];
                mma16(o[0][fn], a[0], bb);
                mma16(o[1][fn], a[1], bb);
            }
        }

        if (t + 1 < 32){
            CP_WAIT0();
            __syncthreads();
        }
    }

    unsigned* Hw = (unsigned*)H;
    #pragma unroll
    for (int fm = 0; fm < 2; fm++)
        #pragma unroll
        for (int hh = 0; hh < 2; hh++){
            float inv = 1.f / l_[fm][hh];
            int sg = qb*256 + w*32 + fm*16 + rr + 8*hh;
            size_t base = ((size_t)b*S_LEN + sg)*512 + hd*32;
            #pragma unroll
            for (int fn = 0; fn < 8; fn++)
                Hw[base + fn*4 + cb] = pk(o[fm][fn][hh*2]*inv, o[fm][fn][hh*2+1]*inv);
        }
}

extern "C" void kernel_launch(void* const* d_in, const int* in_sizes, int n_in,
                              void* d_out, int out_size)
{
    const float* X  = (const float*)d_in[0];
    const float* Wq = (const float*)d_in[1];
    const float* bq = (const float*)d_in[2];
    const float* Wk = (const float*)d_in[3];
    const float* bk = (const float*)d_in[4];
    const float* Wv = (const float*)d_in[5];
    const float* bv = (const float*)d_in[6];
    const float* Wo = (const float*)d_in[7];
    const float* bo = (const float*)d_in[8];
    float* out = (float*)d_out;

    __half *gq, *gk, *gvt, *gh, *gx, *gw;
    cudaGetSymbolAddress((void**)&gq, g_Qh);
    cudaGetSymbolAddress((void**)&gk, g_Kh);
    cudaGetSymbolAddress((void**)&gvt, g_VTh);
    cudaGetSymbolAddress((void**)&gh, g_Hh);
    cudaGetSymbolAddress((void**)&gx, g_Xh);
    cudaGetSymbolAddress((void**)&gw, g_Wh);

    const int attn_smem = 4*2304*4;   // 36864 B
    cudaFuncSetAttribute(attn_h, cudaFuncAttributeMaxDynamicSharedMemorySize, attn_smem);

    rope_table_kernel<<<(S_LEN*512 + 255)/256, 256>>>();

    const int X8 = M_TOT*D_DIM/8, W8 = D_DIM*D_DIM/8;
    conv_f16<<<(X8 + 255)/256, 256>>>(X, gx, X8);
    conv_f16<<<(W8 + 255)/256, 256>>>(Wq, gw + 0*D_DIM*D_DIM, W8);
    conv_f16<<<(W8 + 255)/256, 256>>>(Wk, gw + 1*D_DIM*D_DIM, W8);
    conv_f16<<<(W8 + 255)/256, 256>>>(Wv, gw + 2*D_DIM*D_DIM, W8);
    conv_f16<<<(W8 + 255)/256, 256>>>(Wo, gw + 3*D_DIM*D_DIM, W8);

    const float QS = 0.18033688011112042f;   // 0.125 * log2(e)
    dim3 ggrid(D_DIM/128, M_TOT/128);   // (8, 64)
    gemm_h<2><<<ggrid, 128>>>(gx, gw + 0*D_DIM*D_DIM, bq, gq, QS);
    gemm_h<2><<<ggrid, 128>>>(gx, gw + 1*D_DIM*D_DIM, bk, gk, 1.0f);
    gemm_h<3><<<ggrid, 128>>>(gx, gw + 2*D_DIM*D_DIM, bv, gvt, 1.0f);

    attn_h<<<dim3(S_LEN/256, NH, BATCH), 256, attn_smem>>>(gq, gk, gvt, gh);

    gemm_h<0><<<ggrid, 128>>>(gh, gw + 3*D_DIM*D_DIM, bo, out, 1.0f);
}

// round 17
// speedup vs baseline: 1.3348x; 1.0192x over previous
#include <cuda_runtime.h>
#include <cuda_fp16.h>
#include <math.h>
#include <stdint.h>

#define BATCH 4
#define S_LEN 2048
#define D_DIM 1024
#define NH    16
#define DH    64
#define M_TOT (BATCH*S_LEN)

__device__ __half g_Qh[BATCH*NH*S_LEN*DH];   // holds Q * 0.125*log2(e)
__device__ __half g_Kh[BATCH*NH*S_LEN*DH];
__device__ __half g_VTh[BATCH*NH*DH*S_LEN];  // [b,h][dh][S]
__device__ __half g_Hh[M_TOT*D_DIM];
__device__ __half g_Xh[M_TOT*D_DIM];
__device__ __half g_Wh[4*D_DIM*D_DIM];
__device__ float2 g_tab[S_LEN*(D_DIM/2)];

__device__ __forceinline__ unsigned pk(float a, float b){
    __half2 h = __floats2half2_rn(a, b); return *(unsigned*)&h;
}
__device__ __forceinline__ float ex2(float x){
    float y; asm("ex2.approx.f32 %0, %1;" : "=f"(y) : "f"(x)); return y;
}
__device__ __forceinline__ unsigned ex2h2(unsigned x){
    unsigned y; asm("ex2.approx.f16x2 %0, %1;" : "=r"(y) : "r"(x)); return y;
}
__device__ __forceinline__ uint32_t smem_u32(const void* p){
    uint32_t a;
    asm("{ .reg .u64 t; cvta.to.shared.u64 t, %1; cvt.u32.u64 %0, t; }" : "=r"(a) : "l"(p));
    return a;
}
__device__ __forceinline__ void cp16(uint32_t dst, const void* src){
    asm volatile("cp.async.cg.shared.global [%0], [%1], 16;" :: "r"(dst), "l"(src) : "memory");
}
#define CP_COMMIT() asm volatile("cp.async.commit_group;" ::: "memory")
#define CP_WAIT0()  asm volatile("cp.async.wait_group 0;" ::: "memory")

__device__ __forceinline__ void mma16(float* c, const unsigned* a, const unsigned* b){
    asm volatile("mma.sync.aligned.m16n8k16.row.col.f32.f16.f16.f32 "
        "{%0,%1,%2,%3}, {%4,%5,%6,%7}, {%8,%9}, {%0,%1,%2,%3};"
        : "+f"(c[0]), "+f"(c[1]), "+f"(c[2]), "+f"(c[3])
        : "r"(a[0]), "r"(a[1]), "r"(a[2]), "r"(a[3]), "r"(b[0]), "r"(b[1]));
}

__global__ void rope_table_kernel(){
    int idx = blockIdx.x*blockDim.x + threadIdx.x;
    if (idx >= S_LEN*512) return;
    int s = idx >> 9, p = idx & 511;
    double inv = exp(-((double)(2*p)/(double)D_DIM)*log(10000.0));
    float sn, cs; sincosf((float)s*(float)inv, &sn, &cs);
    g_tab[idx] = make_float2(cs, sn);
}

__global__ void conv_f16(const float* __restrict__ src, __half* __restrict__ dst, int n8){
    int i = blockIdx.x*blockDim.x + threadIdx.x;
    if (i >= n8) return;
    const float4* s = (const float4*)src + (size_t)i*2;
    float4 v0 = s[0], v1 = s[1];
    uint4 o;
    o.x = pk(v0.x, v0.y); o.y = pk(v0.z, v0.w);
    o.z = pk(v1.x, v1.y); o.w = pk(v1.z, v1.w);
    ((uint4*)dst)[i] = o;
}

// ============ fp16 GEMM: out = A[M,1024] @ W[N,1024]^T + bias ============
// MODE 0: fp32 [M,N]+bias; MODE 2: RoPE+qscale+half scatter [B,H,S,dh]; MODE 3: half transposed [B,H,dh,S]
template<int MODE>
__global__ __launch_bounds__(128,2) void gemm_h(
    const __half* __restrict__ A, const __half* __restrict__ W,
    const float* __restrict__ bias, void* __restrict__ outv, float qs)
{
    __shared__ unsigned As[2][8*136], Bs[2][8*136];
    int tid = threadIdx.x, lane = tid & 31, w = tid >> 5;
    int rr = lane >> 2, cb = lane & 3;
    int wm = (w >> 1)*64, wn = (w & 1)*64;
    int m0 = blockIdx.y*128, n0 = blockIdx.x*128;

    float acc[4][8][4];
    #pragma unroll
    for (int i=0;i<4;i++)
        #pragma unroll
        for (int j=0;j<8;j++)
            #pragma unroll
            for (int e=0;e<4;e++) acc[i][j][e] = 0.f;

    const uint4* Ar[2]; const uint4* Wr[2];
    int mm[2], kk[2];
    #pragma unroll
    for (int l=0;l<2;l++){
        int slot = tid + l*128;
        mm[l] = slot >> 1; kk[l] = slot & 1;
        Ar[l] = (const uint4*)A + (size_t)(m0+mm[l])*128;
        Wr[l] = (const uint4*)W + (size_t)(n0+mm[l])*128;
    }

    uint4 av[2], bv[2];
    #pragma unroll
    for (int l=0;l<2;l++){ av[l] = Ar[l][kk[l]]; bv[l] = Wr[l][kk[l]]; }
    #pragma unroll
    for (int l=0;l<2;l++){
        const unsigned* a4 = (const unsigned*)&av[l];
        const unsigned* b4 = (const unsigned*)&bv[l];
        #pragma unroll
        for (int j=0;j<4;j++){
            As[0][(kk[l]*4+j)*136 + ((mm[l] + 8*kk[l]) & 127)] = a4[j];
            Bs[0][(kk[l]*4+j)*136 + ((mm[l] + 8*kk[l]) & 127)] = b4[j];
        }
    }
    __syncthreads();

    for (int it = 0; it < 64; it++){
        int cur = it & 1;
        if (it + 1 < 64){
            #pragma unroll
            for (int l=0;l<2;l++){
                av[l] = Ar[l][(it+1)*2 + kk[l]];
                bv[l] = Wr[l][(it+1)*2 + kk[l]];
            }
        }
        unsigned a[4][4], b[8][2];
        #pragma unroll
        for (int fm = 0; fm < 4; fm++){
            int r = wm + rr + fm*16;
            a[fm][0] = As[cur][cb*136 + (r & 127)];
            a[fm][1] = As[cur][cb*136 + ((r+8) & 127)];
            a[fm][2] = As[cur][(cb+4)*136 + ((r+8) & 127)];
            a[fm][3] = As[cur][(cb+4)*136 + ((r+16) & 127)];
        }
        #pragma unroll
        for (int fn = 0; fn < 8; fn++){
            int n = wn + rr + fn*8;
            b[fn][0] = Bs[cur][cb*136 + (n & 127)];
            b[fn][1] = Bs[cur][(cb+4)*136 + ((n+8) & 127)];
        }
        #pragma unroll
        for (int fm = 0; fm < 4; fm++)
            #pragma unroll
            for (int fn = 0; fn < 8; fn++)
                mma16(acc[fm][fn], a[fm], b[fn]);
        if (it + 1 < 64){
            int nxt = cur ^ 1;
            #pragma unroll
            for (int l=0;l<2;l++){
                const unsigned* a4 = (const unsigned*)&av[l];
                const unsigned* b4 = (const unsigned*)&bv[l];
                #pragma unroll
                for (int j=0;j<4;j++){
                    As[nxt][(kk[l]*4+j)*136 + ((mm[l] + 8*kk[l]) & 127)] = a4[j];
                    Bs[nxt][(kk[l]*4+j)*136 + ((mm[l] + 8*kk[l]) & 127)] = b4[j];
                }
            }
            __syncthreads();
        }
    }

    #pragma unroll
    for (int fn = 0; fn < 8; fn++){
        int colg = n0 + wn + fn*8 + cb*2;
        float b0v = bias[colg], b1v = bias[colg+1];
        #pragma unroll
        for (int fm = 0; fm < 4; fm++){
            #pragma unroll
            for (int half = 0; half < 2; half++){
                int mr = m0 + wm + fm*16 + rr + half*8;
                float v0 = acc[fm][fn][half*2+0] + b0v;
                float v1 = acc[fm][fn][half*2+1] + b1v;
                int srow = mr & (S_LEN-1);
                int bb = mr >> 11, hh = colg >> 6, dd = colg & 63;
                if (MODE == 2){
                    float2 cs = g_tab[srow*512 + (colg >> 1)];
                    float e = v0*cs.x - v1*cs.y;
                    float d = v0*cs.y + v1*cs.x;
                    v0 = e*qs; v1 = d*qs;
                }
                if (MODE == 0){
                    *(float2*)((float*)outv + (size_t)mr*D_DIM + colg) = make_float2(v0, v1);
                } else if (MODE == 2){
                    ((unsigned*)outv)[((size_t)(bb*NH+hh)*S_LEN + srow)*32 + (dd>>1)] = pk(v0, v1);
                } else {  // MODE 3: V transposed [b,h][dh][S]
                    __half* ov = (__half*)outv + ((size_t)(bb*NH+hh)*DH + dd)*S_LEN + srow;
                    ov[0] = __float2half(v0);
                    ov[S_LEN] = __float2half(v1);
                }
            }
        }
    }
}

// ============ fp16 flash attention: 8 warps x 16q x 64k, cp.async K/V, 2 CTAs/SM ============
__global__ __launch_bounds__(256,2) void attn_h(
    const __half* __restrict__ Q, const __half* __restrict__ K,
    const __half* __restrict__ VT, __half* __restrict__ H)
{
    extern __shared__ unsigned sm[];
    // layout (words): K: [0, 2*2304), V: [4608, +2*2304)
    int tid = threadIdx.x, lane = tid & 31, w = tid >> 5;
    int rr = lane >> 2, cb = lane & 3;
    int qb = blockIdx.x, hd = blockIdx.y, b = blockIdx.z;
    int bh = b*NH + hd;

    const unsigned* Qw = (const unsigned*)(Q + ((size_t)bh*S_LEN + qb*128 + w*16)*DH);
    const uint4* Kg = (const uint4*)(K + (size_t)bh*S_LEN*DH);
    const uint4* Vg = (const uint4*)(VT + (size_t)bh*DH*S_LEN);

    int kp0 = tid >> 3, cq0 = tid & 7;           // slot 0: rows 0..31
    int kp1 = kp0 + 32;                          // slot 1: rows 32..63
    uint32_t sb = smem_u32(sm);
    uint32_t kd0 = sb + (kp0*36 + cq0*4)*4, kd1 = sb + (kp1*36 + cq0*4)*4;
    uint32_t vd0 = kd0 + 4608*4, vd1 = kd1 + 4608*4;

    // Q pre-scaled by 0.125*log2e in the projection epilogue; 16 rows per warp
    unsigned q[4][4];
    #pragma unroll
    for (int ks = 0; ks < 4; ks++){
        int kw = ks*8 + cb;
        q[ks][0] = Qw[rr*32 + kw];
        q[ks][1] = Qw[(rr+8)*32 + kw];
        q[ks][2] = Qw[rr*32 + kw + 4];
        q[ks][3] = Qw[(rr+8)*32 + kw + 4];
    }

    float m_[2], l_[2], o[8][4];
    #pragma unroll
    for (int hh=0;hh<2;hh++){ m_[hh] = -1e30f; l_[hh] = 0.f; }
    #pragma unroll
    for (int fn=0;fn<8;fn++)
        #pragma unroll
        for (int e=0;e<4;e++) o[fn][e] = 0.f;

    // prologue: cp.async tile 0 into buffer 0
    cp16(kd0, Kg + (size_t)kp0*8 + cq0);
    cp16(kd1, Kg + (size_t)kp1*8 + cq0);
    cp16(vd0, Vg + (size_t)kp0*256 + cq0);
    cp16(vd1, Vg + (size_t)kp1*256 + cq0);
    CP_COMMIT();
    CP_WAIT0();
    __syncthreads();

    for (int t = 0; t < 32; t++){
        int cur = t & 1;
        const unsigned* Kc = sm + cur*2304;
        const unsigned* Vc = sm + 4608 + cur*2304;
        if (t + 1 < 32){
            uint32_t off = (uint32_t)((cur^1)*2304*4);
            cp16(kd0 + off, Kg + (size_t)((t+1)*64 + kp0)*8 + cq0);
            cp16(kd1 + off, Kg + (size_t)((t+1)*64 + kp1)*8 + cq0);
            cp16(vd0 + off, Vg + (size_t)kp0*256 + (t+1)*8 + cq0);
            cp16(vd1 + off, Vg + (size_t)kp1*256 + (t+1)*8 + cq0);
            CP_COMMIT();
        }

        float s[8][4];
        #pragma unroll
        for (int fn=0;fn<8;fn++)
            #pragma unroll
            for (int e=0;e<4;e++) s[fn][e] = 0.f;

        #pragma unroll
        for (int ks = 0; ks < 4; ks++){
            int kw = ks*8 + cb;
            #pragma unroll
            for (int fn = 0; fn < 8; fn++){
                int n = fn*8 + rr;
                unsigned bb[2];
                bb[0] = Kc[n*36 + kw];
                bb[1] = Kc[n*36 + kw + 4];
                mma16(s[fn], q[ks], bb);
            }
        }

        // base-2 online softmax; exponentials in f16x2 (packed P fragments fall out)
        unsigned p2[8][2];
        #pragma unroll
        for (int hh = 0; hh < 2; hh++){
            float rm = -1e30f;
            #pragma unroll
            for (int fn = 0; fn < 8; fn++)
                rm = fmaxf(rm, fmaxf(s[fn][hh*2], s[fn][hh*2+1]));
            rm = fmaxf(rm, __shfl_xor_sync(0xffffffffu, rm, 1));
            rm = fmaxf(rm, __shfl_xor_sync(0xffffffffu, rm, 2));
            float mn = fmaxf(m_[hh], rm);
            float sum = 0.f;
            #pragma unroll
            for (int fn = 0; fn < 8; fn++){
                float d0 = s[fn][hh*2]   - mn;
                float d1 = s[fn][hh*2+1] - mn;
                unsigned pe = ex2h2(pk(d0, d1));
                p2[fn][hh] = pe;
                float2 f = __half22float2(*(__half2*)&pe);
                sum += f.x + f.y;
            }
            sum += __shfl_xor_sync(0xffffffffu, sum, 1);
            sum += __shfl_xor_sync(0xffffffffu, sum, 2);
            float alpha = ex2(m_[hh] - mn);
            l_[hh] = l_[hh]*alpha + sum;
            m_[hh] = mn;
            #pragma unroll
            for (int fn = 0; fn < 8; fn++){
                o[fn][hh*2]   *= alpha;
                o[fn][hh*2+1] *= alpha;
            }
        }

        // PV: A-fragments are the packed exp results directly
        #pragma unroll
        for (int ks = 0; ks < 4; ks++){
            int kw = ks*8 + cb;
            unsigned a[4];
            a[0] = p2[2*ks][0];
            a[1] = p2[2*ks][1];
            a[2] = p2[2*ks+1][0];
            a[3] = p2[2*ks+1][1];
            #pragma unroll
            for (int fn = 0; fn < 8; fn++){
                int n = fn*8 + rr;
                unsigned bb[2];
                bb[0] = Vc[n*36 + kw];
                bb[1] = Vc[n*36 + kw + 4];
                mma16(o[fn], a, bb);
            }
        }

        if (t + 1 < 32){
            CP_WAIT0();
            __syncthreads();
        }
    }

    unsigned* Hw = (unsigned*)H;
    #pragma unroll
    for (int hh = 0; hh < 2; hh++){
        float inv = 1.f / l_[hh];
        int sg = qb*128 + w*16 + rr + 8*hh;
        size_t base = ((size_t)b*S_LEN + sg)*512 + hd*32;
        #pragma unroll
        for (int fn = 0; fn < 8; fn++)
            Hw[base + fn*4 + cb] = pk(o[fn][hh*2]*inv, o[fn][hh*2+1]*inv);
    }
}

extern "C" void kernel_launch(void* const* d_in, const int* in_sizes, int n_in,
                              void* d_out, int out_size)
{
    const float* X  = (const float*)d_in[0];
    const float* Wq = (const float*)d_in[1];
    const float* bq = (const float*)d_in[2];
    const float* Wk = (const float*)d_in[3];
    const float* bk = (const float*)d_in[4];
    const float* Wv = (const float*)d_in[5];
    const float* bv = (const float*)d_in[6];
    const float* Wo = (const float*)d_in[7];
    const float* bo = (const float*)d_in[8];
    float* out = (float*)d_out;

    __half *gq, *gk, *gvt, *gh, *gx, *gw;
    cudaGetSymbolAddress((void**)&gq, g_Qh);
    cudaGetSymbolAddress((void**)&gk, g_Kh);
    cudaGetSymbolAddress((void**)&gvt, g_VTh);
    cudaGetSymbolAddress((void**)&gh, g_Hh);
    cudaGetSymbolAddress((void**)&gx, g_Xh);
    cudaGetSymbolAddress((void**)&gw, g_Wh);

    const int attn_smem = 4*2304*4;   // 36864 B per CTA
    cudaFuncSetAttribute(attn_h, cudaFuncAttributeMaxDynamicSharedMemorySize, attn_smem);

    rope_table_kernel<<<(S_LEN*512 + 255)/256, 256>>>();

    const int X8 = M_TOT*D_DIM/8, W8 = D_DIM*D_DIM/8;
    conv_f16<<<(X8 + 255)/256, 256>>>(X, gx, X8);
    conv_f16<<<(W8 + 255)/256, 256>>>(Wq, gw + 0*D_DIM*D_DIM, W8);
    conv_f16<<<(W8 + 255)/256, 256>>>(Wk, gw + 1*D_DIM*D_DIM, W8);
    conv_f16<<<(W8 + 255)/256, 256>>>(Wv, gw + 2*D_DIM*D_DIM, W8);
    conv_f16<<<(W8 + 255)/256, 256>>>(Wo, gw + 3*D_DIM*D_DIM, W8);

    const float QS = 0.18033688011112042f;   // 0.125 * log2(e)
    dim3 ggrid(D_DIM/128, M_TOT/128);   // (8, 64)
    gemm_h<2><<<ggrid, 128>>>(gx, gw + 0*D_DIM*D_DIM, bq, gq, QS);
    gemm_h<2><<<ggrid, 128>>>(gx, gw + 1*D_DIM*D_DIM, bk, gk, 1.0f);
    gemm_h<3><<<ggrid, 128>>>(gx, gw + 2*D_DIM*D_DIM, bv, gvt, 1.0f);

    attn_h<<<dim3(S_LEN/128, NH, BATCH), 256, attn_smem>>>(gq, gk, gvt, gh);

    gemm_h<0><<<ggrid, 128>>>(gh, gw + 3*D_DIM*D_DIM, bo, out, 1.0f);
}